// round 6
// baseline (speedup 1.0000x reference)
#include <cuda_runtime.h>
#include <math.h>

#define DCH   128
#define BE    1024
#define NF    128
#define NS    32768
#define NT    256      // threads per CTA

// Dynamic smem (floats)
#define A_OFF    0
#define A_SIZE   (128*36)
#define B_OFF    (A_OFF + A_SIZE)
#define B_SIZE   (128*68)
#define XF_OFF   (B_OFF + B_SIZE)
#define VS_OFF   (XF_OFF + 128)
#define VD_OFF   (VS_OFF + 128)
#define PART_OFF (VD_OFF + 256)
#define SMEM_FLOATS (PART_OFF + 256)
#define SMEM_BYTES  (SMEM_FLOATS * 4)

typedef unsigned long long u64;

__device__ __forceinline__ float leaky(float v) { return v > 0.f ? v : 0.2f * v; }

// Packed f32x2 helpers (sm_100+): exact fp32 per lane, 2 MACs per issue slot.
__device__ __forceinline__ u64 pk(float a, float b) {
    u64 r; asm("mov.b64 %0, {%1,%2};" : "=l"(r) : "f"(a), "f"(b)); return r;
}
__device__ __forceinline__ void upk(u64 v, float& a, float& b) {
    asm("mov.b64 {%0,%1}, %2;" : "=f"(a), "=f"(b) : "l"(v));
}
__device__ __forceinline__ void f2fma(u64& d, u64 a, u64 b) {
    asm("fma.rn.f32x2 %0, %1, %2, %0;" : "+l"(d) : "l"(a), "l"(b));
}

// Transposed conv (k=4, s=2, p=1), JAX conv_transpose (no flip):
//   y[2j]   = sum_ci x[j-1]*w0 + x[j]*w2
//   y[2j+1] = sum_ci x[j]  *w1 + x[j+1]*w3
// Packed: acc2[j] = (y[2j], y[2j+1]);
//   acc2[j] += (x[j-1],x[j])*(w0,w1);  acc2[j] += (x[j],x[j+1])*(w2,w3)

// Variant A: thread (co, h in {0,1}) — used for the small first layer.
template <int LIN, int SIN, int SOUT>
__device__ __forceinline__ void tconv(
    const float* __restrict__ W, const float* __restrict__ bias,
    const float* __restrict__ xin, float* __restrict__ yout,
    int co, int h, bool act)
{
    constexpr int NJ = LIN / 2;
    constexpr int NC = NJ / 4;
    const float bv = bias[co];
    u64 acc[NJ];
    {
        u64 bp = pk(bv, bv);
#pragma unroll
        for (int j = 0; j < NJ; ++j) acc[j] = bp;
    }
    const int j0 = h * NJ;

    for (int ci = 0; ci < DCH; ++ci) {
        float4 w = *(const float4*)(W + ((ci * DCH + co) << 2));
        u64 w01 = pk(w.x, w.y);
        u64 w23 = pk(w.z, w.w);
        const float* xr = xin + ci * SIN + j0;
        float prev = (h == 0) ? 0.f : xr[-1];
        float xend = (h == 1) ? 0.f : xr[NJ];
        const float4* xv = (const float4*)xr;
        float4 c = xv[0];
        u64 p0 = pk(prev, c.x);
#pragma unroll
        for (int m = 0; m < NC; ++m) {
            float nx; float4 cn;
            if (m + 1 < NC) { cn = xv[m + 1]; nx = cn.x; }
            else            { cn = c;         nx = xend; }
            u64 p1 = pk(c.x, c.y);
            u64 p2 = pk(c.y, c.z);
            u64 p3 = pk(c.z, c.w);
            u64 p4 = pk(c.w, nx);
            f2fma(acc[4*m+0], p0, w01); f2fma(acc[4*m+0], p1, w23);
            f2fma(acc[4*m+1], p1, w01); f2fma(acc[4*m+1], p2, w23);
            f2fma(acc[4*m+2], p2, w01); f2fma(acc[4*m+2], p3, w23);
            f2fma(acc[4*m+3], p3, w01); f2fma(acc[4*m+3], p4, w23);
            p0 = p4;
            c = cn;
        }
    }

    float* yr = yout + co * SOUT + 2 * j0;
#pragma unroll
    for (int m = 0; m < NJ / 2; ++m) {
        float a0, a1, b0, b1;
        upk(acc[2*m],   a0, a1);
        upk(acc[2*m+1], b0, b1);
        float4 v;
        v.x = act ? leaky(a0) : a0;
        v.y = act ? leaky(a1) : a1;
        v.z = act ? leaky(b0) : b0;
        v.w = act ? leaky(b1) : b1;
        *(float4*)(yr + 4*m) = v;
    }
}

// Variant B: co-blocked x2, thread (c2 in 0..63, h in 0..3).
// Computes channels co0=2*c2, co1=co0+1 over the h-th quarter of positions.
// x-window pairs built once, shared by both channels.
template <int LIN, int SIN, int SOUT>
__device__ __forceinline__ void tconv_cb2(
    const float* __restrict__ W, const float* __restrict__ bias,
    const float* __restrict__ xin, float* __restrict__ yout,
    int c2, int h, bool act)
{
    constexpr int NJ = LIN / 4;          // j positions per thread (per channel)
    constexpr int NC = NJ / 4;
    const int co0 = 2 * c2;
    const int co1 = co0 + 1;
    u64 accA[NJ], accB[NJ];
    {
        u64 bA = pk(bias[co0], bias[co0]);
        u64 bB = pk(bias[co1], bias[co1]);
#pragma unroll
        for (int j = 0; j < NJ; ++j) { accA[j] = bA; accB[j] = bB; }
    }
    const int j0 = h * NJ;

    for (int ci = 0; ci < DCH; ++ci) {
        const float4* wp = (const float4*)(W + ((ci * DCH + co0) << 2));
        float4 wa = wp[0];
        float4 wb = wp[1];
        u64 wa01 = pk(wa.x, wa.y), wa23 = pk(wa.z, wa.w);
        u64 wb01 = pk(wb.x, wb.y), wb23 = pk(wb.z, wb.w);
        const float* xr = xin + ci * SIN + j0;
        float prev = (h == 0) ? 0.f : xr[-1];
        float xend = (h == 3) ? 0.f : xr[NJ];
        const float4* xv = (const float4*)xr;
        float4 c = xv[0];
        u64 p0 = pk(prev, c.x);
#pragma unroll
        for (int m = 0; m < NC; ++m) {
            float nx; float4 cn;
            if (m + 1 < NC) { cn = xv[m + 1]; nx = cn.x; }
            else            { cn = c;         nx = xend; }
            u64 p1 = pk(c.x, c.y);
            u64 p2 = pk(c.y, c.z);
            u64 p3 = pk(c.z, c.w);
            u64 p4 = pk(c.w, nx);
            f2fma(accA[4*m+0], p0, wa01); f2fma(accA[4*m+0], p1, wa23);
            f2fma(accA[4*m+1], p1, wa01); f2fma(accA[4*m+1], p2, wa23);
            f2fma(accA[4*m+2], p2, wa01); f2fma(accA[4*m+2], p3, wa23);
            f2fma(accA[4*m+3], p3, wa01); f2fma(accA[4*m+3], p4, wa23);
            f2fma(accB[4*m+0], p0, wb01); f2fma(accB[4*m+0], p1, wb23);
            f2fma(accB[4*m+1], p1, wb01); f2fma(accB[4*m+1], p2, wb23);
            f2fma(accB[4*m+2], p2, wb01); f2fma(accB[4*m+2], p3, wb23);
            f2fma(accB[4*m+3], p3, wb01); f2fma(accB[4*m+3], p4, wb23);
            p0 = p4;
            c = cn;
        }
    }

    float* yr0 = yout + co0 * SOUT + 2 * j0;   // 2*j0 multiple of 4 (NJ>=4 even)
    float* yr1 = yout + co1 * SOUT + 2 * j0;
#pragma unroll
    for (int m = 0; m < NJ / 2; ++m) {
        float a0, a1, b0, b1;
        upk(accA[2*m],   a0, a1);
        upk(accA[2*m+1], b0, b1);
        float4 v;
        v.x = act ? leaky(a0) : a0;
        v.y = act ? leaky(a1) : a1;
        v.z = act ? leaky(b0) : b0;
        v.w = act ? leaky(b1) : b1;
        *(float4*)(yr0 + 4*m) = v;
        upk(accB[2*m],   a0, a1);
        upk(accB[2*m+1], b0, b1);
        v.x = act ? leaky(a0) : a0;
        v.y = act ? leaky(a1) : a1;
        v.z = act ? leaky(b0) : b0;
        v.w = act ? leaky(b1) : b1;
        *(float4*)(yr1 + 4*m) = v;
    }
}

__global__ void __launch_bounds__(NT, 3) npg_kernel(
    const float* __restrict__ x,    const float* __restrict__ noise,
    const float* __restrict__ Wup,  const float* __restrict__ bup,
    const float* __restrict__ Wd0,  const float* __restrict__ bd0,
    const float* __restrict__ Wd1,  const float* __restrict__ bd1,
    const float* __restrict__ Wd2,  const float* __restrict__ bd2,
    const float* __restrict__ Wdo,  const float* __restrict__ bdo,
    const float* __restrict__ Wc0,  const float* __restrict__ bc0,
    const float* __restrict__ Wc1,  const float* __restrict__ bc1,
    const float* __restrict__ Wc2,  const float* __restrict__ bc2,
    const float* __restrict__ Wc3,  const float* __restrict__ bc3,
    float* __restrict__ out)
{
    extern __shared__ float smem[];
    float*  A    = smem + A_OFF;
    float*  B    = smem + B_OFF;
    float*  xf   = smem + XF_OFF;
    float*  vseq = smem + VS_OFF;
    float2* vd   = (float2*)(smem + VD_OFF);
    float*  part = smem + PART_OFF;
    __shared__ float s_decay;

    const int row  = blockIdx.x;
    const int t    = threadIdx.x;
    const int lane = t & 31;
    const int warp = t >> 5;
    const int co   = t & 127;
    const int h    = t >> 7;

    if (t < DCH) xf[t] = x[row * DCH + t];
    __syncthreads();

    // ---------------- decay head: 3x (D->D leaky) -> D->1 sigmoid ----------------
    {
        float* h0 = A;
        float* h1 = A + DCH;
        if (t < DCH) h0[t] = xf[t];
        __syncthreads();
        const float* Ws[3] = {Wd0, Wd1, Wd2};
        const float* bs[3] = {bd0, bd1, bd2};
        float* cur = h0;
        float* nxt = h1;
        for (int L = 0; L < 3; ++L) {
            const float* W = Ws[L];
            const int d0 = h * 64;
            float s0 = 0.f, s1 = 0.f, s2 = 0.f, s3 = 0.f;
            for (int dd = d0; dd < d0 + 64; dd += 4) {
                s0 += cur[dd+0] * W[(dd+0) * DCH + co];
                s1 += cur[dd+1] * W[(dd+1) * DCH + co];
                s2 += cur[dd+2] * W[(dd+2) * DCH + co];
                s3 += cur[dd+3] * W[(dd+3) * DCH + co];
            }
            part[t] = (s0 + s1) + (s2 + s3);
            __syncthreads();
            if (t < DCH) nxt[t] = leaky(bs[L][t] + part[t] + part[t + 128]);
            __syncthreads();
            float* tmp = cur; cur = nxt; nxt = tmp;
        }
        float p = (t < DCH) ? cur[t] * Wdo[t] : 0.f;
#pragma unroll
        for (int off = 16; off > 0; off >>= 1) p += __shfl_xor_sync(0xffffffffu, p, off);
        if (lane == 0) part[warp] = p;
        __syncthreads();
        if (t == 0) {
            float s = bdo[0];
            for (int wgi = 0; wgi < NT / 32; ++wgi) s += part[wgi];
            s_decay = 0.8f + 0.2f / (1.f + expf(-s));
        }
        __syncthreads();
    }

    // ---------------- up projection: xf @ Wup -> [128][8] into A (stride 12) -----
    {
        float4 bvv = *(const float4*)(bup + co * 8 + 4 * h);
        u64 a01 = pk(bvv.x, bvv.y);
        u64 a23 = pk(bvv.z, bvv.w);
        const float* wr = Wup + co * 8 + 4 * h;
        for (int dd = 0; dd < DCH; ++dd) {
            float4 w = *(const float4*)(wr + dd * (DCH * 8));
            float xvv = xf[dd];
            u64 xx = pk(xvv, xvv);
            f2fma(a01, xx, pk(w.x, w.y));
            f2fma(a23, xx, pk(w.z, w.w));
        }
        __syncthreads();   // decay phase fully done with A
        float4 o;
        upk(a01, o.x, o.y);
        upk(a23, o.z, o.w);
        *(float4*)(A + co * 12 + 4 * h) = o;
        __syncthreads();
    }

    // ---------------- transposed conv stack: 8 -> 16 -> 32 -> 64 -----------------
    tconv<8, 12, 20>(Wc0, bc0, A, B, co, h, true);
    __syncthreads();
    tconv_cb2<16, 20, 36>(Wc1, bc1, B, A, t & 63, t >> 6, true);
    __syncthreads();
    tconv_cb2<32, 36, 68>(Wc2, bc2, A, B, t & 63, t >> 6, true);
    __syncthreads();

    // ---------------- final tconv to 1 channel (64 -> 128), square ---------------
    {
        const int  p  = co;
        const int  j  = p >> 1;
        const bool ev = (p & 1) == 0;
        const int  ia = ev ? (j - 1) : j;
        const int  ib = ev ? j : (j + 1);
        const bool va = ia >= 0;
        const bool vb = ib <= 63;
        const int  c0 = h * 64;
        float acc = 0.f;
        for (int ci = c0; ci < c0 + 64; ++ci) {
            float4 w = *(const float4*)(Wc3 + (ci << 2));
            const float* xr = B + ci * 68;
            float xa = va ? xr[ia] : 0.f;
            float xb = vb ? xr[ib] : 0.f;
            float ca = ev ? w.x : w.y;
            float cb = ev ? w.z : w.w;
            acc += xa * ca + xb * cb;
        }
        part[t] = acc;
        __syncthreads();
        if (t < NF) {
            float v = bc3[0] + part[t] + part[t + 128];
            vseq[t] = v * v;
        }
    }
    __syncthreads();

    // ---------------- exponential decay recurrence: warp scan --------------------
    if (warp == 0) {
        const float d = s_decay;
        float4 u = *(const float4*)(vseq + lane * 4);
        float p0 = u.x;
        float p1 = fmaf(d, p0, u.y);
        float p2 = fmaf(d, p1, u.z);
        float p3 = fmaf(d, p2, u.w);
        const float d2 = d * d;
        const float d4 = d2 * d2;
        float V = p3;
        float m = d4;
#pragma unroll
        for (int off = 1; off < 32; off <<= 1) {
            float up = __shfl_up_sync(0xffffffffu, V, off);
            if (lane >= off) V = fmaf(m, up, V);
            m = m * m;
        }
        float C = __shfl_up_sync(0xffffffffu, V, 1);
        if (lane == 0) C = 0.f;
        float4 o;
        o.x = fmaf(C, d,      p0);
        o.y = fmaf(C, d2,     p1);
        o.z = fmaf(C, d2 * d, p2);
        o.w = fmaf(C, d4,     p3);
        *(float4*)(vseq + lane * 4) = o;
    }
    __syncthreads();
    // fused (value, slope) pairs; vd[127].y = 0 absorbs the i1 clamp
    if (t < NF) {
        float a = vseq[t];
        float b = (t < NF - 1) ? (vseq[t + 1] - a) : 0.f;
        vd[t] = make_float2(a, b);
    }
    __syncthreads();

    // ---------------- linear interp 128 -> 32768, multiply by noise --------------
    // pos(n) = (n+0.5)/256 - 0.5; per iter n += 1024 => pos += 4.0 exactly, so the
    // fractional weight is loop-invariant and i0 += 4. Only iter 0 can clamp low;
    // the high side never clamps (max pos = 127.498) and dv[127]=0 covers i1.
    {
        const float4* np_ = (const float4*)(noise + (size_t)row * NS);
        float4*       op  = (float4*)(out + (size_t)row * NS);

        // iteration 0 (peeled, with low clamp)
        {
            float4 nz = np_[t];
            float4 r;
#pragma unroll
            for (int k = 0; k < 4; ++k) {
                float pos = fmaf((float)(4 * t + k), 0.00390625f, -0.498046875f);
                pos = fmaxf(pos, 0.f);
                int   i0 = (int)pos;
                float w  = pos - (float)i0;
                float2 s = vd[i0];
                ((float*)&r)[k] = fmaf(w, s.y, s.x) * ((const float*)&nz)[k];
            }
            op[t] = r;
        }

        // steady state: iterations 1..31
        int   i0v[4];
        float wv[4];
#pragma unroll
        for (int k = 0; k < 4; ++k) {
            float pos = fmaf((float)(4 * t + k + 1024), 0.00390625f, -0.498046875f);
            int   i = (int)pos;
            i0v[k] = i;
            wv[k]  = pos - (float)i;
        }
#pragma unroll 4
        for (int m = 1; m < 32; ++m) {
            float4 nz = np_[t + m * NT];
            float4 r;
#pragma unroll
            for (int k = 0; k < 4; ++k) {
                float2 s = vd[i0v[k]];
                ((float*)&r)[k] = fmaf(wv[k], s.y, s.x) * ((const float*)&nz)[k];
                i0v[k] += 4;
            }
            op[t + m * NT] = r;
        }
    }
}

extern "C" void kernel_launch(void* const* d_in, const int* in_sizes, int n_in,
                              void* d_out, int out_size)
{
    (void)in_sizes; (void)n_in; (void)out_size;
    const float* x    = (const float*)d_in[0];
    const float* noise= (const float*)d_in[1];
    const float* Wup  = (const float*)d_in[2];
    const float* bup  = (const float*)d_in[3];
    const float* Wd0  = (const float*)d_in[4];
    const float* bd0  = (const float*)d_in[5];
    const float* Wd1  = (const float*)d_in[6];
    const float* bd1  = (const float*)d_in[7];
    const float* Wd2  = (const float*)d_in[8];
    const float* bd2  = (const float*)d_in[9];
    const float* Wdo  = (const float*)d_in[10];
    const float* bdo  = (const float*)d_in[11];
    const float* Wc0  = (const float*)d_in[12];
    const float* bc0  = (const float*)d_in[13];
    const float* Wc1  = (const float*)d_in[14];
    const float* bc1  = (const float*)d_in[15];
    const float* Wc2  = (const float*)d_in[16];
    const float* bc2  = (const float*)d_in[17];
    const float* Wc3  = (const float*)d_in[18];
    const float* bc3  = (const float*)d_in[19];
    float* out = (float*)d_out;

    cudaFuncSetAttribute(npg_kernel, cudaFuncAttributeMaxDynamicSharedMemorySize, SMEM_BYTES);
    npg_kernel<<<BE, NT, SMEM_BYTES>>>(
        x, noise, Wup, bup, Wd0, bd0, Wd1, bd1, Wd2, bd2, Wdo, bdo,
        Wc0, bc0, Wc1, bc1, Wc2, bc2, Wc3, bc3, out);
}